// round 11
// baseline (speedup 1.0000x reference)
#include <cuda_runtime.h>

#define NN       50000
#define HC       128
#define NEG      0.2f
#define SCAP     256
#define MAXTGT   1024
#define HCAP     128               // per-block local hit buffer
#define BMWORDS  ((NN + 31) / 32)

// ---------------- device scratch ----------------
__device__ unsigned g_bitmap[BMWORDS];
__device__ int      g_nodelist[SCAP];
__device__ int      g_tgt_src[MAXTGT];
__device__ float    g_tgt_a[MAXTGT];
__device__ float    g_ssum[4 * SCAP];
__device__ float    g_xl2[SCAP * HC];
__device__ float    g_xr2t[HC];
__device__ int      g_tcount, g_nnodes;
__device__ double   g_easum;
__device__ float    g_sink;

__device__ __forceinline__ float lrelu(float v) { return v > 0.f ? v : NEG * v; }

// rare-path: process a hit when the shared buffer overflows (never in practice)
__device__ __noinline__ void hit_overflow(
        int slot, float xs, float xd, float a,
        const float* __restrict__ Wl1, const float* __restrict__ bl1,
        const float* __restrict__ Wr1, const float* __restrict__ br1,
        const float* __restrict__ We1, const float* __restrict__ att1) {
    float p0 = 0.f, p1 = 0.f;
    for (int j = 0; j < HC; j++) {
        float bb = __ldg(bl1 + j) + __ldg(br1 + j);
        float v = fmaf(xs, __ldg(Wl1 + j), fmaf(a, __ldg(We1 + j), fmaf(xd, __ldg(Wr1 + j), bb)));
        v = lrelu(v);
        float p = v * __ldg(att1 + j);
        if (j < 64) p0 += p; else p1 += p;
    }
    float e0 = expf(p0), e1 = expf(p1);
    atomicAdd(&g_ssum[4 * slot],     e0);
    atomicAdd(&g_ssum[4 * slot + 1], e1);
    atomicAdd(&g_ssum[4 * slot + 2], e0 * xs);
    atomicAdd(&g_ssum[4 * slot + 3], e1 * xs);
}

// ---------------- K0: reset + L2 prefetch ----------------
__global__ void k_reset(const int* tgtp,
                        const float* __restrict__ Wl2, const float* __restrict__ Wr2,
                        const float* __restrict__ Wfc, const float* __restrict__ x,
                        const float* __restrict__ Wl1, const float* __restrict__ Wr1,
                        const float* __restrict__ We1, const float* __restrict__ att1,
                        const float* __restrict__ bl1, const float* __restrict__ br1,
                        const float* __restrict__ b1) {
    int tid = threadIdx.x;
    float acc = 0.f;
    if (blockIdx.x < 8) {
        int tgt = *tgtp;
        int i = blockIdx.x * blockDim.x + tid;
        int stride = 8 * blockDim.x;
        int tw = tgt >> 5;
        for (int j = i; j < BMWORDS; j += stride)
            g_bitmap[j] = (j == tw) ? (1u << (tgt & 31)) : 0u;
        for (int j = i; j < 4 * SCAP; j += stride) g_ssum[j] = 0.f;
        if (i == 0) {
            g_tcount = 0; g_nnodes = 1; g_easum = 0.0;
            g_nodelist[0] = tgt;
        }
        return;
    } else if (blockIdx.x < 56) {
        int b = blockIdx.x - 8;
        const float* W = (b % 3 == 0) ? Wl2 : (b % 3 == 1) ? Wr2 : Wfc;
        int nb = 16, sub = b / 3;
        const float4* W4 = (const float4*)W;
        int nv = (HC * HC) / 4;
        for (int j = sub * blockDim.x + tid; j < nv; j += nb * blockDim.x) {
            float4 v = W4[j];
            acc += v.x + v.y + v.z + v.w;
        }
    } else if (blockIdx.x < 63) {
        int sub = blockIdx.x - 56;
        const float4* x4 = (const float4*)x;
        int nv = NN / 4;
        for (int j = sub * blockDim.x + tid; j < nv; j += 7 * blockDim.x) {
            float4 v = x4[j];
            acc += v.x + v.y + v.z + v.w;
        }
    } else {
        if (tid < HC)
            acc = Wl1[tid] + Wr1[tid] + We1[tid] + att1[tid]
                + bl1[tid] + br1[tid] + b1[tid];
    }
    if (acc == 123456789.0f) g_sink = acc;
}

// ---------------- K1: scan dst: target in-edges + flag sources ----------------
__global__ void k_scan1(const int* __restrict__ src, const int* __restrict__ dst,
                        const float* __restrict__ ea, const int* tgtp, int E) {
    int tgt = *tgtp;
    int i = blockIdx.x * blockDim.x + threadIdx.x;
    int stride = gridDim.x * blockDim.x;
    int nv = E >> 2;
    const int4* d4 = (const int4*)dst;
    for (int v = i; v < nv; v += stride) {
        int4 d = d4[v];
        int e = v << 2;
        #pragma unroll
        for (int c = 0; c < 4; c++) {
            int dd = (c == 0) ? d.x : (c == 1) ? d.y : (c == 2) ? d.z : d.w;
            if (dd == tgt) {
                int idx = atomicAdd(&g_tcount, 1);
                int s = src[e + c];
                if (idx < MAXTGT) { g_tgt_src[idx] = s; g_tgt_a[idx] = ea[e + c]; }
                unsigned m = 1u << (s & 31);
                unsigned old = atomicOr(&g_bitmap[s >> 5], m);
                if (!(old & m)) {
                    int sl = atomicAdd(&g_nnodes, 1);
                    if (sl < SCAP) g_nodelist[sl] = s;
                }
            }
        }
    }
    for (int e = (nv << 2) + i; e < E; e += stride) {
        if (dst[e] == tgt) {
            int idx = atomicAdd(&g_tcount, 1);
            int s = src[e];
            if (idx < MAXTGT) { g_tgt_src[idx] = s; g_tgt_a[idx] = ea[e]; }
            unsigned m = 1u << (s & 31);
            unsigned old = atomicOr(&g_bitmap[s >> 5], m);
            if (!(old & m)) {
                int sl = atomicAdd(&g_nnodes, 1);
                if (sl < SCAP) g_nodelist[sl] = s;
            }
        }
    }
}

// ---------------- K2: scan + ea sum + local hit buffer + conv1 partial sums ----------------
__global__ void k_scan2(const int* __restrict__ src, const int* __restrict__ dst,
                        const float* __restrict__ ea, const float* __restrict__ x,
                        const float* __restrict__ Wl1, const float* __restrict__ bl1,
                        const float* __restrict__ Wr1, const float* __restrict__ br1,
                        const float* __restrict__ We1, const float* __restrict__ att1,
                        int E) {
    __shared__ unsigned sbm[BMWORDS];
    __shared__ int snl[SCAP];
    __shared__ int snn, scnt;
    __shared__ int   hslot[HCAP];
    __shared__ float hxs[HCAP], hxd[HCAP], ha[HCAP];
    __shared__ float sWl[HC], sWr[HC], sWe[HC], sAt[HC], sBlr[HC];

    int tid = threadIdx.x;
    int i = blockIdx.x * blockDim.x + tid;
    int stride = gridDim.x * blockDim.x;

    for (int j = tid; j < BMWORDS; j += blockDim.x) sbm[j] = g_bitmap[j];
    if (tid == 0) { snn = min(g_nnodes, SCAP); scnt = 0; }
    __syncthreads();
    int nn = snn;
    for (int j = tid; j < nn; j += blockDim.x) snl[j] = g_nodelist[j];
    __syncthreads();

    int nv = E >> 2;
    const int4* d4 = (const int4*)dst;
    const float4* a4 = (const float4*)ea;
    float ax = 0.f, ay = 0.f, az = 0.f, aw = 0.f;
    for (int v = i; v < nv; v += stride) {
        int4 d = d4[v];
        float4 a = a4[v];
        ax += a.x; ay += a.y; az += a.z; aw += a.w;
        int e = v << 2;
        #pragma unroll
        for (int c = 0; c < 4; c++) {
            int dd = (c == 0) ? d.x : (c == 1) ? d.y : (c == 2) ? d.z : d.w;
            if ((sbm[dd >> 5] >> (dd & 31)) & 1u) {
                float aa = (c == 0) ? a.x : (c == 1) ? a.y : (c == 2) ? a.z : a.w;
                int slot = 0;
                for (int t = 0; t < nn; t++) { if (snl[t] == dd) { slot = t; break; } }
                float xs = x[src[e + c]], xd = x[dd];
                int idx = atomicAdd(&scnt, 1);
                if (idx < HCAP) {
                    hslot[idx] = slot; hxs[idx] = xs; hxd[idx] = xd; ha[idx] = aa;
                } else {
                    hit_overflow(slot, xs, xd, aa, Wl1, bl1, Wr1, br1, We1, att1);
                }
            }
        }
    }
    for (int e = (nv << 2) + i; e < E; e += stride) {
        int dd = dst[e];
        ax += ea[e];
        if ((sbm[dd >> 5] >> (dd & 31)) & 1u) {
            int slot = 0;
            for (int t = 0; t < nn; t++) { if (snl[t] == dd) { slot = t; break; } }
            float xs = x[src[e]], xd = x[dd];
            int idx = atomicAdd(&scnt, 1);
            if (idx < HCAP) {
                hslot[idx] = slot; hxs[idx] = xs; hxd[idx] = xd; ha[idx] = ea[e];
            } else {
                hit_overflow(slot, xs, xd, ea[e], Wl1, bl1, Wr1, br1, We1, att1);
            }
        }
    }
    __syncthreads();

    // ---- post-loop: conv1 logits for this block's hits ----
    int cnt = min(scnt, HCAP);
    if (cnt > 0) {
        if (tid < HC) {
            sWl[tid] = Wl1[tid]; sWr[tid] = Wr1[tid]; sWe[tid] = We1[tid];
            sAt[tid] = att1[tid]; sBlr[tid] = bl1[tid] + br1[tid];
        }
        __syncthreads();
        for (int k = tid; k < cnt; k += blockDim.x) {
            int slot = hslot[k];
            float xs = hxs[k], xd = hxd[k], a = ha[k];
            float p0 = 0.f, p1 = 0.f;
            #pragma unroll 8
            for (int j = 0; j < HC; j++) {
                float v = fmaf(xs, sWl[j], fmaf(a, sWe[j], fmaf(xd, sWr[j], sBlr[j])));
                v = lrelu(v);
                float p = v * sAt[j];
                if (j < 64) p0 += p; else p1 += p;
            }
            float e0 = expf(p0), e1 = expf(p1);   // logits bounded; no max needed
            atomicAdd(&g_ssum[4 * slot],     e0);
            atomicAdd(&g_ssum[4 * slot + 1], e1);
            atomicAdd(&g_ssum[4 * slot + 2], e0 * xs);
            atomicAdd(&g_ssum[4 * slot + 3], e1 * xs);
        }
    }

    // ---- ea sum reduction ----
    __shared__ double sd[256];
    sd[tid] = (double)((ax + ay) + (az + aw)); __syncthreads();
    for (int off = blockDim.x >> 1; off; off >>= 1) {
        if (tid < off) sd[tid] += sd[tid + off];
        __syncthreads();
    }
    if (tid == 0) atomicAdd(&g_easum, sd[0]);
}

// ---------------- K3: GEMM — self-loop fold + h1 + xl2 per slot; block 63: xr2t ----------------
__global__ void __launch_bounds__(512) k_gemm(
        const float* __restrict__ x,
        const float* __restrict__ Wl1, const float* __restrict__ bl1,
        const float* __restrict__ Wr1, const float* __restrict__ br1,
        const float* __restrict__ We1, const float* __restrict__ att1,
        const float* __restrict__ b1,
        const float* __restrict__ Wl2, const float* __restrict__ bl2,
        const float* __restrict__ Wr2, const float* __restrict__ br2, int E) {
    int tid = threadIdx.x, c = tid & 127, q = tid >> 7;
    int nn = min(g_nnodes, SCAP);
    float fill = (float)(g_easum / (double)E);
    bool last = (blockIdx.x == 63);

    __shared__ float sh[HC];
    __shared__ float sred[3][HC];
    __shared__ float sws[4];
    __shared__ float sxdv, sS0, sS1;

    float wl = 0.f, wsum = 0.f, we = 0.f, at = 0.f, blr = 0.f, b1c = 0.f;
    if (tid < HC) {
        wl = Wl1[tid];
        wsum = wl + Wr1[tid];
        we = We1[tid]; at = att1[tid];
        blr = bl1[tid] + br1[tid];
        b1c = bl1[tid] + b1[tid];
    }
    const float* W  = last ? Wr2 : Wl2;
    const float* bb = last ? br2 : bl2;

    for (int s = last ? 0 : (int)blockIdx.x; s < nn; s += 63) {
        // ---- self-loop logit for slot s, folded into S ----
        if (tid == 0) sxdv = x[g_nodelist[s]];
        __syncthreads();
        float xd = sxdv;
        if (tid < HC) {
            float v = lrelu(fmaf(xd, wsum, fmaf(fill, we, blr))) * at;
            #pragma unroll
            for (int off = 16; off; off >>= 1)
                v += __shfl_down_sync(0xffffffffu, v, off);
            if ((tid & 31) == 0) sws[tid >> 5] = v;
        }
        __syncthreads();
        if (tid == 0) {
            float e0 = expf(sws[0] + sws[1]);
            float e1 = expf(sws[2] + sws[3]);
            sS0 = (g_ssum[4 * s + 2] + e0 * xd) / (g_ssum[4 * s]     + e0);
            sS1 = (g_ssum[4 * s + 3] + e1 * xd) / (g_ssum[4 * s + 1] + e1);
        }
        __syncthreads();
        if (tid < HC)
            sh[tid] = fmaxf(fmaf(wl, (tid < 64) ? sS0 : sS1, b1c), 0.f);
        __syncthreads();

        // ---- mat-vec vs W (k split 4-way) ----
        float acc = 0.f;
        const float* Wp = W + (q * 32) * HC + c;
        #pragma unroll
        for (int k = 0; k < 32; k++)
            acc = fmaf(sh[q * 32 + k], Wp[k * HC], acc);
        if (q > 0) sred[q - 1][c] = acc;
        __syncthreads();
        if (q == 0) {
            float r = acc + sred[0][c] + sred[1][c] + sred[2][c] + bb[c];
            if (last) g_xr2t[c] = r;
            else      g_xl2[s * HC + c] = r;
        }
        __syncthreads();
        if (last) break;
    }
}

// ---------------- K4: conv2 at target + fc (no-max softmax) ----------------
__global__ void __launch_bounds__(512) k_final(
        const float* __restrict__ We2, const float* __restrict__ att2,
        const float* __restrict__ b2,
        const float* __restrict__ Wfc, const float* __restrict__ bfc,
        float* __restrict__ out, int E) {
    int tid = threadIdx.x, lane = tid & 31, w = tid >> 5;
    int c = tid & 127, q = tid >> 7;
    int nn = min(g_nnodes, SCAP);
    int tc = min(g_tcount, MAXTGT);
    int items = tc + 1;
    float fill = (float)(g_easum / (double)E);

    __shared__ float sxr[HC], sO[HC];
    __shared__ float sred2[3][HC];
    __shared__ int   snl[SCAP];
    __shared__ float sal0[MAXTGT + 1], sal1[MAXTGT + 1];
    __shared__ int   sslot[MAXTGT + 1];
    __shared__ float tsum0, tsum1;

    if (tid < HC) sxr[tid] = g_xr2t[tid];
    for (int j = tid; j < nn; j += 512) snl[j] = g_nodelist[j];
    if (tid == 0) { tsum0 = 0.f; tsum1 = 0.f; }
    __syncthreads();

    for (int i = w; i < items; i += 16) {
        int slot = 0; float a;
        if (i < tc) {
            int sn = g_tgt_src[i];
            for (int t = 0; t < nn; t++) { if (snl[t] == sn) { slot = t; break; } }
            a = g_tgt_a[i];
        } else { slot = 0; a = fill; }
        float p0 = 0.f, p1 = 0.f;
        #pragma unroll
        for (int k = 0; k < 4; k++) {
            int cc = lane + 32 * k;
            float vv = g_xl2[slot * HC + cc] + sxr[cc] + a * We2[cc];
            vv = lrelu(vv);
            float p = vv * att2[cc];
            if (k < 2) p0 += p; else p1 += p;
        }
        #pragma unroll
        for (int off = 16; off; off >>= 1) {
            p0 += __shfl_down_sync(0xffffffffu, p0, off);
            p1 += __shfl_down_sync(0xffffffffu, p1, off);
        }
        if (lane == 0) {
            float e0 = expf(p0), e1 = expf(p1);
            sal0[i] = e0; sal1[i] = e1;
            sslot[i] = slot;
            atomicAdd(&tsum0, e0); atomicAdd(&tsum1, e1);
        }
    }
    __syncthreads();

    float inv = (c < 64) ? (1.f / tsum0) : (1.f / tsum1);
    float agg = 0.f;
    for (int i = q; i < items; i += 4) {
        float al = ((c < 64) ? sal0[i] : sal1[i]) * inv;
        agg = fmaf(al, g_xl2[sslot[i] * HC + c], agg);
    }
    if (q > 0) sred2[q - 1][c] = agg;
    __syncthreads();
    if (q == 0) sO[c] = agg + sred2[0][c] + sred2[1][c] + sred2[2][c] + b2[c];
    __syncthreads();

    float r = 0.f;
    const float* Wf = Wfc + (q * 32) * HC + c;
    #pragma unroll
    for (int k = 0; k < 32; k++)
        r = fmaf(sO[q * 32 + k], Wf[k * HC], r);
    if (q > 0) sred2[q - 1][c] = r;
    __syncthreads();
    if (q == 0) out[c] = r + sred2[0][c] + sred2[1][c] + sred2[2][c] + bfc[c];
}

// ---------------- launch ----------------
extern "C" void kernel_launch(void* const* d_in, const int* in_sizes, int n_in,
                              void* d_out, int out_size) {
    const float* x    = (const float*)d_in[0];
    const int*   ei   = (const int*)  d_in[1];
    const float* ea   = (const float*)d_in[2];
    const int*   tgtp = (const int*)  d_in[3];
    const float* Wl1  = (const float*)d_in[4];
    const float* bl1  = (const float*)d_in[5];
    const float* Wr1  = (const float*)d_in[6];
    const float* br1  = (const float*)d_in[7];
    const float* We1  = (const float*)d_in[8];
    const float* att1 = (const float*)d_in[9];
    const float* b1   = (const float*)d_in[10];
    const float* Wl2  = (const float*)d_in[11];
    const float* bl2  = (const float*)d_in[12];
    const float* Wr2  = (const float*)d_in[13];
    const float* br2  = (const float*)d_in[14];
    const float* We2  = (const float*)d_in[15];
    const float* att2 = (const float*)d_in[16];
    const float* b2   = (const float*)d_in[17];
    const float* Wfc  = (const float*)d_in[18];
    const float* bfc  = (const float*)d_in[19];
    float* out = (float*)d_out;

    int E = in_sizes[1] / 2;
    const int* src = ei;
    const int* dst = ei + E;

    k_reset<<<64, 256>>>(tgtp, Wl2, Wr2, Wfc, x, Wl1, Wr1, We1, att1, bl1, br1, b1);
    k_scan1<<<592, 256>>>(src, dst, ea, tgtp, E);
    k_scan2<<<592, 256>>>(src, dst, ea, x, Wl1, bl1, Wr1, br1, We1, att1, E);
    k_gemm <<<64, 512>>>(x, Wl1, bl1, Wr1, br1, We1, att1, b1, Wl2, bl2, Wr2, br2, E);
    k_final<<<1, 512>>>(We2, att2, b2, Wfc, bfc, out, E);
    (void)n_in; (void)out_size;
}